// round 2
// baseline (speedup 1.0000x reference)
#include <cuda_runtime.h>

typedef unsigned long long ull;

#define NPATH 13

// ---------------- static device scratch (allocation-free rule) ----------------
__device__ float g_cg[573];                     // scaled real-basis CG, all 13 paths
__device__ float g_T0[65536ull * 384];          // io=0: rows z,        cols (pl,u)
__device__ float g_T1[65536ull * 3 * 640];      // io=1: rows z*3+k,    cols (pl,u)
__device__ float g_T2[65536ull * 5 * 640];      // io=2: rows z*5+k,    cols (pl,u)

// path tables (INS order)
__device__ const int c_L1[NPATH]   = {0,0,0,1,1,1,1,1,2,2,2,2,2};
__device__ const int c_L2[NPATH]   = {0,1,2,0,1,1,2,3,0,1,2,2,3};
__device__ const int c_LO[NPATH]   = {0,1,2,1,0,2,1,2,2,1,0,2,1};
__device__ const int c_CGOFF[NPATH]= {0,1,10,35,44,53,98,143,248,273,318,343,468};
__device__ const int c_MSZ[NPATH]  = {1,3,5,9,3,15,9,15,25,15,5,25,15};
__device__ const int c_MOFF[NPATH] = {0,1,4,9,18,21,36,45,60,85,100,105,130};
__device__ const int c_YOFF[4]     = {0,1,4,9};
// weight base offsets (elements) for each io-group's local path order
__device__ const int c_PB[3][5] = {
  {0,      65536,  163840, 0,      0     },   // io0: paths {0,4,10}
  {16384,  49152,  98304,  147456, 196608},   // io1: paths {1,3,6,9,12}
  {32768,  81920,  114688, 131072, 180224}    // io2: paths {2,5,7,8,11}
};

// ---------------- CG computation (fp64, ported 1:1 from reference) ----------------
__device__ double dfact(int n){ double r = 1.0; for (int i = 2; i <= n; ++i) r *= (double)i; return r; }

__device__ double su2_cg(int j1,int m1,int j2,int m2,int j3,int m3){
  if (m3 != m1 + m2) return 0.0;
  int vmin = max(max(-j1 + j2 + m3, -j1 + m1), 0);
  int vmax = min(min(j2 + j3 + m1, j3 - j1 + j2), j3 + m3);
  double C = sqrt((double)(2*j3+1) * dfact(j3+j1-j2) * dfact(j3-j1+j2) * dfact(j1+j2-j3)
                  * dfact(j3+m3) * dfact(j3-m3)
                  / (dfact(j1+j2+j3+1) * dfact(j1-m1) * dfact(j1+m1) * dfact(j2-m2) * dfact(j2+m2)));
  double S = 0.0;
  for (int v = vmin; v <= vmax; ++v){
    double sg = ((v + j2 + m2) & 1) ? -1.0 : 1.0;
    S += sg * dfact(j2+j3+m1-v) * dfact(j1-m1+v)
         / (dfact(v) * dfact(j3-j1+j2-v) * dfact(j3+m3-v) * dfact(v+j1-j2-m3));
  }
  return C * S;
}

__device__ void build_q(int l, double (*qr)[7], double (*qi)[7]){
  for (int a = 0; a < 7; ++a) for (int b = 0; b < 7; ++b){ qr[a][b] = 0.0; qi[a][b] = 0.0; }
  double s = 1.0 / sqrt(2.0);
  for (int m = -l; m < 0; ++m){
    qr[l+m][l-m] = s;       // q[l+m, l+|m|] = 1/sqrt2
    qi[l+m][l+m] = -s;      // q[l+m, l-|m|] = -1j/sqrt2
  }
  qr[l][l] = 1.0;
  for (int m = 1; m <= l; ++m){
    double sg = (m & 1) ? -1.0 : 1.0;
    qr[l+m][l+m] = sg * s;  // (-1)^m / sqrt2
    qi[l+m][l-m] = sg * s;  // 1j*(-1)^m / sqrt2
  }
  int ph = l & 3;           // multiply by (-1j)^l
  if (ph){
    for (int a = 0; a < 2*l+1; ++a) for (int b = 0; b < 2*l+1; ++b){
      double re = qr[a][b], im = qi[a][b];
      if (ph == 1){ qr[a][b] =  im; qi[a][b] = -re; }
      else if (ph == 2){ qr[a][b] = -re; qi[a][b] = -im; }
      else { qr[a][b] = -im; qi[a][b] =  re; }
    }
  }
}

__global__ void cg_kernel(){
  int p = threadIdx.x;
  if (p >= NPATH) return;
  int l1 = c_L1[p], l2 = c_L2[p], l3 = c_LO[p];
  int d1 = 2*l1+1, d2 = 2*l2+1, d3 = 2*l3+1;

  double Ccg[5][7][5];
  for (int a = 0; a < 5; ++a) for (int b = 0; b < 7; ++b) for (int c = 0; c < 5; ++c) Ccg[a][b][c] = 0.0;
  for (int m1 = -l1; m1 <= l1; ++m1)
    for (int m2 = -l2; m2 <= l2; ++m2){
      int m3 = m1 + m2;
      if (m3 >= -l3 && m3 <= l3)
        Ccg[l1+m1][l2+m2][l3+m3] = su2_cg(l1, m1, l2, m2, l3, m3);
    }

  double q1r[7][7], q1i[7][7], q2r[7][7], q2i[7][7], q3r[7][7], q3i[7][7];
  build_q(l1, q1r, q1i); build_q(l2, q2r, q2i); build_q(l3, q3r, q3i);

  double outv[5][7][5];
  double norm2 = 0.0;
  for (int j = 0; j < d1; ++j)
    for (int l = 0; l < d2; ++l)
      for (int m = 0; m < d3; ++m){
        double re = 0.0;
        for (int i = 0; i < d1; ++i){
          double a1r = q1r[i][j], a1i = q1i[i][j];
          if (a1r == 0.0 && a1i == 0.0) continue;
          for (int k = 0; k < d2; ++k){
            double a2r = q2r[k][l], a2i = q2i[k][l];
            if (a2r == 0.0 && a2i == 0.0) continue;
            double ar = a1r*a2r - a1i*a2i;
            double ai = a1r*a2i + a1i*a2r;
            for (int n = 0; n < d3; ++n){
              double c = Ccg[i][k][n];
              if (c == 0.0) continue;
              double q3re = q3r[n][m], q3im = -q3i[n][m];  // conj
              re += c * (ar*q3re - ai*q3im);
            }
          }
        }
        outv[j][l][m] = re;
        norm2 += re * re;
      }
  double cio = (l3 == 0) ? sqrt(1.0/384.0) : (l3 == 1 ? sqrt(3.0/640.0) : sqrt(5.0/640.0));
  double inv = cio / sqrt(norm2);
  for (int j = 0; j < d1; ++j)
    for (int l = 0; l < d2; ++l)
      for (int m = 0; m < d3; ++m)
        g_cg[c_CGOFF[p] + (j*d2 + l)*d3 + m] = (float)(outv[j][l][m] * inv);
}

// ---------------- T build: per-node CG contraction -> GEMM-ready layout ----------------
#define ZB 8
__global__ void __launch_bounds__(256) t_build(const float* __restrict__ x,
                                               const float* __restrict__ y){
  __shared__ float xs[ZB * 1152];
  __shared__ float ys[ZB * 16];
  __shared__ float Ms[ZB * 145];

  int z0  = blockIdx.x * ZB;
  int tid = threadIdx.x;

  for (int idx = tid; idx < ZB*1152; idx += 256) xs[idx] = x[(size_t)z0*1152 + idx];
  for (int idx = tid; idx < ZB*16;   idx += 256) ys[idx] = y[(size_t)z0*16 + idx];
  __syncthreads();

  // M_p[i][k] = sum_j cg_p[i,j,k] * y[j]   (145 values per node; c_io folded into cg)
  for (int idx = tid; idx < ZB*145; idx += 256){
    int zl = idx / 145, e0 = idx % 145;
    int e = e0, p = 0;
    while (e >= c_MSZ[p]){ e -= c_MSZ[p]; ++p; }
    int l2 = c_L2[p], lo = c_LO[p];
    int d2 = 2*l2+1, dlo = 2*lo+1;
    int i = e / dlo, k = e % dlo;
    const float* cg = g_cg + c_CGOFF[p] + (i*d2)*dlo + k;
    const float* yy = ys + zl*16 + c_YOFF[l2];
    float s = 0.f;
    for (int j = 0; j < d2; ++j) s += cg[j*dlo] * yy[j];
    Ms[zl*145 + e0] = s;
  }
  __syncthreads();

  int u  = tid & 127;
  int zh = tid >> 7;
  for (int zl = zh; zl < ZB; zl += 2){
    const float* xz = xs + zl*1152;
    const float* M  = Ms + zl*145;
    float x0 = xz[u];
    float xa = xz[128 + u*3 + 0], xb = xz[128 + u*3 + 1], xc = xz[128 + u*3 + 2];
    float x2v[5];
    #pragma unroll
    for (int i = 0; i < 5; ++i) x2v[i] = xz[512 + u*5 + i];
    int z = z0 + zl;

    { // io0: paths {0,4,10} -> M offsets 0, 18(3x1), 100(5x1)
      float* T = g_T0 + (size_t)z * 384;
      T[0*128 + u] = x0 * M[0];
      T[1*128 + u] = xa*M[18] + xb*M[19] + xc*M[20];
      float s = 0.f;
      #pragma unroll
      for (int i = 0; i < 5; ++i) s += x2v[i] * M[100 + i];
      T[2*128 + u] = s;
    }
    #pragma unroll
    for (int k = 0; k < 3; ++k){ // io1: paths {1,3,6,9,12} -> M 1(1x3), 9(3x3), 36(3x3), 85(5x3), 130(5x3)
      float* T = g_T1 + ((size_t)z*3 + k) * 640;
      T[0*128 + u] = x0 * M[1 + k];
      T[1*128 + u] = xa*M[9  + 0*3 + k] + xb*M[9  + 1*3 + k] + xc*M[9  + 2*3 + k];
      T[2*128 + u] = xa*M[36 + 0*3 + k] + xb*M[36 + 1*3 + k] + xc*M[36 + 2*3 + k];
      float s3 = 0.f, s4 = 0.f;
      #pragma unroll
      for (int i = 0; i < 5; ++i){ s3 += x2v[i]*M[85 + i*3 + k]; s4 += x2v[i]*M[130 + i*3 + k]; }
      T[3*128 + u] = s3;
      T[4*128 + u] = s4;
    }
    #pragma unroll
    for (int k = 0; k < 5; ++k){ // io2: paths {2,5,7,8,11} -> M 4(1x5), 21(3x5), 45(3x5), 60(5x5), 105(5x5)
      float* T = g_T2 + ((size_t)z*5 + k) * 640;
      T[0*128 + u] = x0 * M[4 + k];
      T[1*128 + u] = xa*M[21 + 0*5 + k] + xb*M[21 + 1*5 + k] + xc*M[21 + 2*5 + k];
      T[2*128 + u] = xa*M[45 + 0*5 + k] + xb*M[45 + 1*5 + k] + xc*M[45 + 2*5 + k];
      float s3 = 0.f, s4 = 0.f;
      #pragma unroll
      for (int i = 0; i < 5; ++i){ s3 += x2v[i]*M[60 + i*5 + k]; s4 += x2v[i]*M[105 + i*5 + k]; }
      T[3*128 + u] = s3;
      T[4*128 + u] = s4;
    }
  }
}

// ---------------- GEMM: C[M x 128] = T_io[M x K] @ W_io[K x 128], FFMA2 ----------------
__device__ __forceinline__ ull pack2(float a, float b){
  ull r; asm("mov.b64 %0, {%1, %2};" : "=l"(r) : "f"(a), "f"(b)); return r;
}
__device__ __forceinline__ void fma2(ull& d, ull a, ull b){
  asm("fma.rn.f32x2 %0, %1, %2, %0;" : "+l"(d) : "l"(a), "l"(b));
}
__device__ __forceinline__ void unpack2(ull v, float& a, float& b){
  asm("mov.b64 {%0, %1}, %2;" : "=f"(a), "=f"(b) : "l"(v));
}

__global__ void __launch_bounds__(256) gemm_tp(const float* __restrict__ W,
                                               float* __restrict__ out,
                                               int io, int K, int nk, int obase){
  __shared__ float As[16][68];   // padded to avoid 16-way store conflicts, 16B aligned rows
  __shared__ float Bs[16][128];

  const float* A = (io == 0) ? g_T0 : (io == 1) ? g_T1 : g_T2;
  int pb[5];
  #pragma unroll
  for (int i = 0; i < 5; ++i) pb[i] = c_PB[io][i];

  int tid  = threadIdx.x;
  int row0 = blockIdx.x * 64;
  int n0 = (tid & 31) * 4;
  int m0 = (tid >> 5) * 8;

  ull acc[8][2];
  #pragma unroll
  for (int i = 0; i < 8; ++i){ acc[i][0] = 0ull; acc[i][1] = 0ull; }

  for (int k0 = 0; k0 < K; k0 += 16){
    #pragma unroll
    for (int i = 0; i < 4; ++i){           // A tile 64x16
      int idx = tid + i*256;
      int m = idx >> 4, kk = idx & 15;
      As[kk][m] = A[(size_t)(row0 + m) * K + k0 + kk];
    }
    #pragma unroll
    for (int i = 0; i < 8; ++i){           // B tile 16x128 (weights indexed in place)
      int idx = tid + i*256;
      int krow = idx >> 7, w = idx & 127;
      int kg = k0 + krow;
      Bs[krow][w] = W[pb[kg >> 7] + (kg & 127)*128 + w];
    }
    __syncthreads();
    #pragma unroll
    for (int kk = 0; kk < 16; ++kk){
      float4 a0 = *(const float4*)&As[kk][m0];
      float4 a1 = *(const float4*)&As[kk][m0 + 4];
      float4 b  = *(const float4*)&Bs[kk][n0];
      ull b0 = pack2(b.x, b.y), b1 = pack2(b.z, b.w);
      float av[8] = {a0.x, a0.y, a0.z, a0.w, a1.x, a1.y, a1.z, a1.w};
      #pragma unroll
      for (int i = 0; i < 8; ++i){
        ull aa = pack2(av[i], av[i]);
        fma2(acc[i][0], aa, b0);
        fma2(acc[i][1], aa, b1);
      }
    }
    __syncthreads();
  }

  #pragma unroll
  for (int i = 0; i < 8; ++i){
    float c0, c1, c2, c3;
    unpack2(acc[i][0], c0, c1);
    unpack2(acc[i][1], c2, c3);
    int row = row0 + m0 + i;
    int z = row / nk, kq = row % nk;
    float* o = out + (size_t)z*1152 + obase + kq;
    o[(n0 + 0)*nk] = c0;
    o[(n0 + 1)*nk] = c1;
    o[(n0 + 2)*nk] = c2;
    o[(n0 + 3)*nk] = c3;
  }
}

// ---------------- launch ----------------
extern "C" void kernel_launch(void* const* d_in, const int* in_sizes, int n_in,
                              void* d_out, int out_size){
  const float* x = (const float*)d_in[0];
  const float* y = (const float*)d_in[1];
  const float* w = (const float*)d_in[2];
  float* out = (float*)d_out;
  int n = in_sizes[0] / 1152;   // 65536

  cg_kernel<<<1, 32>>>();
  t_build<<<n / ZB, 256>>>(x, y);
  gemm_tp<<<(n    ) / 64, 256>>>(w, out, 0, 384, 1, 0);
  gemm_tp<<<(n * 3) / 64, 256>>>(w, out, 1, 640, 3, 128);
  gemm_tp<<<(n * 5) / 64, 256>>>(w, out, 2, 640, 5, 512);
}

// round 4
// speedup vs baseline: 1.8842x; 1.8842x over previous
#include <cuda_runtime.h>
#include <cuda_fp16.h>
#include <cstdint>

#define NPATH 13
#define KC 64
#define SMEM_SZ 131072

// ---------------- static device scratch ----------------
__device__ __align__(256) float g_cg[573];
__device__ __align__(256) __half g_T0h[65536ull*384];
__device__ __align__(256) __half g_T0l[65536ull*384];
__device__ __align__(256) __half g_T1h[196608ull*640];
__device__ __align__(256) __half g_T1l[196608ull*640];
__device__ __align__(256) __half g_T2h[327680ull*640];
__device__ __align__(256) __half g_T2l[327680ull*640];
__device__ __align__(256) __half g_Wh[3*128*640];
__device__ __align__(256) __half g_Wl[3*128*640];

__device__ const int c_L1[NPATH]   = {0,0,0,1,1,1,1,1,2,2,2,2,2};
__device__ const int c_L2[NPATH]   = {0,1,2,0,1,1,2,3,0,1,2,2,3};
__device__ const int c_LO[NPATH]   = {0,1,2,1,0,2,1,2,2,1,0,2,1};
__device__ const int c_CGOFF[NPATH]= {0,1,10,35,44,53,98,143,248,273,318,343,468};
__device__ const int c_MSZ[NPATH]  = {1,3,5,9,3,15,9,15,25,15,5,25,15};
__device__ const int c_YOFF[4]     = {0,1,4,9};
__device__ const int c_PB[3][5] = {
  {0,      65536,  163840, 0,      0     },
  {16384,  49152,  98304,  147456, 196608},
  {32768,  81920,  114688, 131072, 180224}
};

// ---------------- CG computation (fp64, ported from reference) ----------------
__device__ double dfact(int n){ double r = 1.0; for (int i = 2; i <= n; ++i) r *= (double)i; return r; }

__device__ double su2_cg(int j1,int m1,int j2,int m2,int j3,int m3){
  if (m3 != m1 + m2) return 0.0;
  int vmin = max(max(-j1 + j2 + m3, -j1 + m1), 0);
  int vmax = min(min(j2 + j3 + m1, j3 - j1 + j2), j3 + m3);
  double C = sqrt((double)(2*j3+1) * dfact(j3+j1-j2) * dfact(j3-j1+j2) * dfact(j1+j2-j3)
                  * dfact(j3+m3) * dfact(j3-m3)
                  / (dfact(j1+j2+j3+1) * dfact(j1-m1) * dfact(j1+m1) * dfact(j2-m2) * dfact(j2+m2)));
  double S = 0.0;
  for (int v = vmin; v <= vmax; ++v){
    double sg = ((v + j2 + m2) & 1) ? -1.0 : 1.0;
    S += sg * dfact(j2+j3+m1-v) * dfact(j1-m1+v)
         / (dfact(v) * dfact(j3-j1+j2-v) * dfact(j3+m3-v) * dfact(v+j1-j2-m3));
  }
  return C * S;
}

__device__ void build_q(int l, double (*qr)[7], double (*qi)[7]){
  for (int a = 0; a < 7; ++a) for (int b = 0; b < 7; ++b){ qr[a][b] = 0.0; qi[a][b] = 0.0; }
  double s = 1.0 / sqrt(2.0);
  for (int m = -l; m < 0; ++m){ qr[l+m][l-m] = s; qi[l+m][l+m] = -s; }
  qr[l][l] = 1.0;
  for (int m = 1; m <= l; ++m){
    double sg = (m & 1) ? -1.0 : 1.0;
    qr[l+m][l+m] = sg * s; qi[l+m][l-m] = sg * s;
  }
  int ph = l & 3;
  if (ph){
    for (int a = 0; a < 2*l+1; ++a) for (int b = 0; b < 2*l+1; ++b){
      double re = qr[a][b], im = qi[a][b];
      if (ph == 1){ qr[a][b] =  im; qi[a][b] = -re; }
      else if (ph == 2){ qr[a][b] = -re; qi[a][b] = -im; }
      else { qr[a][b] = -im; qi[a][b] =  re; }
    }
  }
}

__global__ void cg_kernel(){
  int p = threadIdx.x;
  if (p >= NPATH) return;
  int l1 = c_L1[p], l2 = c_L2[p], l3 = c_LO[p];
  int d1 = 2*l1+1, d2 = 2*l2+1, d3 = 2*l3+1;

  double Ccg[5][7][5];
  for (int a = 0; a < 5; ++a) for (int b = 0; b < 7; ++b) for (int c = 0; c < 5; ++c) Ccg[a][b][c] = 0.0;
  for (int m1 = -l1; m1 <= l1; ++m1)
    for (int m2 = -l2; m2 <= l2; ++m2){
      int m3 = m1 + m2;
      if (m3 >= -l3 && m3 <= l3)
        Ccg[l1+m1][l2+m2][l3+m3] = su2_cg(l1, m1, l2, m2, l3, m3);
    }

  double q1r[7][7], q1i[7][7], q2r[7][7], q2i[7][7], q3r[7][7], q3i[7][7];
  build_q(l1, q1r, q1i); build_q(l2, q2r, q2i); build_q(l3, q3r, q3i);

  double outv[5][7][5];
  double norm2 = 0.0;
  for (int j = 0; j < d1; ++j)
    for (int l = 0; l < d2; ++l)
      for (int m = 0; m < d3; ++m){
        double re = 0.0;
        for (int i = 0; i < d1; ++i){
          double a1r = q1r[i][j], a1i = q1i[i][j];
          if (a1r == 0.0 && a1i == 0.0) continue;
          for (int k = 0; k < d2; ++k){
            double a2r = q2r[k][l], a2i = q2i[k][l];
            if (a2r == 0.0 && a2i == 0.0) continue;
            double ar = a1r*a2r - a1i*a2i;
            double ai = a1r*a2i + a1i*a2r;
            for (int n = 0; n < d3; ++n){
              double c = Ccg[i][k][n];
              if (c == 0.0) continue;
              re += c * (ar*q3r[n][m] - ai*(-q3i[n][m]));
            }
          }
        }
        outv[j][l][m] = re;
        norm2 += re * re;
      }
  double cio = (l3 == 0) ? sqrt(1.0/384.0) : (l3 == 1 ? sqrt(3.0/640.0) : sqrt(5.0/640.0));
  double inv = cio / sqrt(norm2);
  for (int j = 0; j < d1; ++j)
    for (int l = 0; l < d2; ++l)
      for (int m = 0; m < d3; ++m)
        g_cg[c_CGOFF[p] + (j*d2 + l)*d3 + m] = (float)(outv[j][l][m] * inv);
}

// ---------------- weight transpose + split: B[n][k] hi/lo fp16 ----------------
__global__ void wprep(const float* __restrict__ w){
  int idx = blockIdx.x * 256 + threadIdx.x;
  if (idx >= 3*128*640) return;
  int g = idx / (128*640);
  int rem = idx - g*128*640;
  int n = rem / 640, k = rem % 640;
  int K = (g == 0) ? 384 : 640;
  float v = 0.f;
  if (k < K) v = w[c_PB[g][k >> 7] + (k & 127)*128 + n];
  __half h = __float2half_rn(v);
  g_Wh[idx] = h;
  g_Wl[idx] = __float2half_rn(v - __half2float(h));
}

// ---------------- T build ----------------
__device__ __forceinline__ void wsp(__half* ph, __half* pl, float v){
  __half h = __float2half_rn(v);
  *ph = h; *pl = __float2half_rn(v - __half2float(h));
}

#define ZB 8
__global__ void __launch_bounds__(256) t_build(const float* __restrict__ x,
                                               const float* __restrict__ y){
  __shared__ float xs[ZB * 1152];
  __shared__ float ys[ZB * 16];
  __shared__ float Ms[ZB * 145];

  int z0  = blockIdx.x * ZB;
  int tid = threadIdx.x;

  for (int idx = tid; idx < ZB*1152; idx += 256) xs[idx] = x[(size_t)z0*1152 + idx];
  for (int idx = tid; idx < ZB*16;   idx += 256) ys[idx] = y[(size_t)z0*16 + idx];
  __syncthreads();

  for (int idx = tid; idx < ZB*145; idx += 256){
    int zl = idx / 145, e0 = idx % 145;
    int e = e0, p = 0;
    while (e >= c_MSZ[p]){ e -= c_MSZ[p]; ++p; }
    int l2 = c_L2[p], lo = c_LO[p];
    int d2 = 2*l2+1, dlo = 2*lo+1;
    int i = e / dlo, k = e % dlo;
    const float* cg = g_cg + c_CGOFF[p] + (i*d2)*dlo + k;
    const float* yy = ys + zl*16 + c_YOFF[l2];
    float s = 0.f;
    for (int j = 0; j < d2; ++j) s += cg[j*dlo] * yy[j];
    Ms[zl*145 + e0] = s;
  }
  __syncthreads();

  int u  = tid & 127;
  int zh = tid >> 7;
  for (int zl = zh; zl < ZB; zl += 2){
    const float* xz = xs + zl*1152;
    const float* M  = Ms + zl*145;
    float x0 = xz[u];
    float xa = xz[128 + u*3 + 0], xb = xz[128 + u*3 + 1], xc = xz[128 + u*3 + 2];
    float x2v[5];
    #pragma unroll
    for (int i = 0; i < 5; ++i) x2v[i] = xz[512 + u*5 + i];
    size_t z = z0 + zl;

    { // io0: rows = z, K=384
      size_t b = z * 384 + u;
      wsp(g_T0h + b,       g_T0l + b,       x0 * M[0]);
      wsp(g_T0h + b + 128, g_T0l + b + 128, xa*M[18] + xb*M[19] + xc*M[20]);
      float s = 0.f;
      #pragma unroll
      for (int i = 0; i < 5; ++i) s += x2v[i] * M[100 + i];
      wsp(g_T0h + b + 256, g_T0l + b + 256, s);
    }
    #pragma unroll
    for (int k = 0; k < 3; ++k){ // io1: rows = k*65536 + z, K=640
      size_t b = ((size_t)k*65536 + z) * 640 + u;
      wsp(g_T1h + b,       g_T1l + b,       x0 * M[1 + k]);
      wsp(g_T1h + b + 128, g_T1l + b + 128, xa*M[9 + k] + xb*M[12 + k] + xc*M[15 + k]);
      wsp(g_T1h + b + 256, g_T1l + b + 256, xa*M[36 + k] + xb*M[39 + k] + xc*M[42 + k]);
      float s3 = 0.f, s4 = 0.f;
      #pragma unroll
      for (int i = 0; i < 5; ++i){ s3 += x2v[i]*M[85 + i*3 + k]; s4 += x2v[i]*M[130 + i*3 + k]; }
      wsp(g_T1h + b + 384, g_T1l + b + 384, s3);
      wsp(g_T1h + b + 512, g_T1l + b + 512, s4);
    }
    #pragma unroll
    for (int k = 0; k < 5; ++k){ // io2: rows = k*65536 + z, K=640
      size_t b = ((size_t)k*65536 + z) * 640 + u;
      wsp(g_T2h + b,       g_T2l + b,       x0 * M[4 + k]);
      wsp(g_T2h + b + 128, g_T2l + b + 128, xa*M[21 + k] + xb*M[26 + k] + xc*M[31 + k]);
      wsp(g_T2h + b + 256, g_T2l + b + 256, xa*M[45 + k] + xb*M[50 + k] + xc*M[55 + k]);
      float s3 = 0.f, s4 = 0.f;
      #pragma unroll
      for (int i = 0; i < 5; ++i){ s3 += x2v[i]*M[60 + i*5 + k]; s4 += x2v[i]*M[105 + i*5 + k]; }
      wsp(g_T2h + b + 384, g_T2l + b + 384, s3);
      wsp(g_T2h + b + 512, g_T2l + b + 512, s4);
    }
  }
}

// ---------------- mma.sync GEMM ----------------
__device__ __forceinline__ uint32_t smem_u32(const void* p){
  uint32_t a;
  asm("{ .reg .u64 t; cvta.to.shared.u64 t, %1; cvt.u32.u64 %0, t; }" : "=r"(a) : "l"(p));
  return a;
}
#define SWZ(off) ((off) ^ (((off) >> 3) & 0x70))

__device__ __forceinline__ void cp16(uint32_t dst, const void* src){
  asm volatile("cp.async.cg.shared.global [%0], [%1], 16;" :: "r"(dst), "l"(src) : "memory");
}
__device__ __forceinline__ void cp_commit(){ asm volatile("cp.async.commit_group;" ::: "memory"); }
template<int N> __device__ __forceinline__ void cp_wait(){ asm volatile("cp.async.wait_group %0;" :: "n"(N) : "memory"); }

__device__ __forceinline__ void ldsm4(uint32_t* r, uint32_t addr){
  asm volatile("ldmatrix.sync.aligned.m8n8.x4.shared.b16 {%0,%1,%2,%3}, [%4];"
    : "=r"(r[0]), "=r"(r[1]), "=r"(r[2]), "=r"(r[3]) : "r"(addr));
}
__device__ __forceinline__ void mma16816(float* c, const uint32_t* a, uint32_t b0, uint32_t b1){
  asm volatile("mma.sync.aligned.m16n8k16.row.col.f32.f16.f16.f32 "
    "{%0,%1,%2,%3}, {%4,%5,%6,%7}, {%8,%9}, {%0,%1,%2,%3};"
    : "+f"(c[0]), "+f"(c[1]), "+f"(c[2]), "+f"(c[3])
    : "r"(a[0]), "r"(a[1]), "r"(a[2]), "r"(a[3]), "r"(b0), "r"(b1));
}

__global__ void __launch_bounds__(256, 1) gemm_mma(float* __restrict__ out,
                                                   int io, int K, int nk, int obase){
  extern __shared__ __align__(1024) char smem[];
  uint32_t sb = smem_u32(smem);
  int tid = threadIdx.x, wid = tid >> 5, lane = tid & 31;

  const __half *pAh, *pAl;
  if (io == 0){ pAh = g_T0h; pAl = g_T0l; }
  else if (io == 1){ pAh = g_T1h; pAl = g_T1l; }
  else { pAh = g_T2h; pAl = g_T2l; }
  const __half* pBh = g_Wh + io*128*640;
  const __half* pBl = g_Wl + io*128*640;

  int kq = blockIdx.x % nk;
  int zt = blockIdx.x / nk;
  size_t row0 = (size_t)kq*65536 + (size_t)zt*128;
  int C = K / KC;

  int m0 = (wid & 3) * 32;
  int n0 = (wid >> 2) * 64;

  float acc[2][8][4];
  #pragma unroll
  for (int a = 0; a < 2; ++a)
    #pragma unroll
    for (int b = 0; b < 8; ++b)
      #pragma unroll
      for (int c = 0; c < 4; ++c) acc[a][b][c] = 0.f;

  // prologue: chunk 0
  {
    uint32_t st = sb;
    #pragma unroll
    for (int i = 0; i < 4; ++i){
      int idx = tid + i*256;
      int r = idx >> 3, sg = idx & 7;
      uint32_t d = st + SWZ(r*128 + sg*16);
      size_t ga = (row0 + r)*(size_t)K + sg*8;
      size_t gb = (size_t)r*640 + sg*8;
      cp16(d,         pAh + ga);
      cp16(d + 16384, pAl + ga);
      cp16(d + 32768, pBh + gb);
      cp16(d + 49152, pBl + gb);
    }
    cp_commit();
  }

  // per-lane fragment addressing offsets
  int rA = (lane & 7) + (lane & 8);          // + m0 + mt*16
  int cAb = (lane >> 4) << 4;                // byte col offset
  int rB = (lane & 7) + ((lane >> 4) << 3);  // + n0 + bt*16
  int cBb = ((lane >> 3) & 1) << 4;

  for (int c = 0; c < C; ++c){
    if (c + 1 < C){
      int s = (c + 1) & 1;
      uint32_t st = sb + s*65536;
      int k0 = (c + 1) * KC;
      #pragma unroll
      for (int i = 0; i < 4; ++i){
        int idx = tid + i*256;
        int r = idx >> 3, sg = idx & 7;
        uint32_t d = st + SWZ(r*128 + sg*16);
        size_t ga = (row0 + r)*(size_t)K + k0 + sg*8;
        size_t gb = (size_t)r*640 + k0 + sg*8;
        cp16(d,         pAh + ga);
        cp16(d + 16384, pAl + ga);
        cp16(d + 32768, pBh + gb);
        cp16(d + 49152, pBl + gb);
      }
      cp_commit();
      cp_wait<1>();
    } else {
      cp_wait<0>();
    }
    __syncthreads();

    int s = c & 1;
    uint32_t stAh = sb + s*65536;
    uint32_t stAl = stAh + 16384;
    uint32_t stBh = stAh + 32768;
    uint32_t stBl = stAh + 49152;

    #pragma unroll
    for (int kk = 0; kk < 4; ++kk){
      int cb = kk*32;
      uint32_t ah[2][4], al[2][4];
      #pragma unroll
      for (int mt = 0; mt < 2; ++mt){
        int off = (m0 + mt*16 + rA)*128 + cb + cAb;
        ldsm4(ah[mt], stAh + SWZ(off));
        ldsm4(al[mt], stAl + SWZ(off));
      }
      uint32_t bh[4][4], bl[4][4];
      #pragma unroll
      for (int bt = 0; bt < 4; ++bt){
        int off = (n0 + bt*16 + rB)*128 + cb + cBb;
        ldsm4(bh[bt], stBh + SWZ(off));
        ldsm4(bl[bt], stBl + SWZ(off));
      }
      #pragma unroll
      for (int mt = 0; mt < 2; ++mt)
        #pragma unroll
        for (int nt = 0; nt < 8; ++nt){
          int bt = nt >> 1, rp = (nt & 1) * 2;
          mma16816(acc[mt][nt], ah[mt], bh[bt][rp], bh[bt][rp+1]);
          mma16816(acc[mt][nt], al[mt], bh[bt][rp], bh[bt][rp+1]);
          mma16816(acc[mt][nt], ah[mt], bl[bt][rp], bl[bt][rp+1]);
        }
    }
    __syncthreads();
  }

  // epilogue: accumulators -> smem -> coalesced(ish) global
  float* Csh = (float*)smem;   // [128][132]
  #pragma unroll
  for (int mt = 0; mt < 2; ++mt)
    #pragma unroll
    for (int nt = 0; nt < 8; ++nt){
      int r = m0 + mt*16 + (lane >> 2);
      int cc = n0 + nt*8 + (lane & 3)*2;
      Csh[r*132 + cc]       = acc[mt][nt][0];
      Csh[r*132 + cc + 1]   = acc[mt][nt][1];
      Csh[(r+8)*132 + cc]   = acc[mt][nt][2];
      Csh[(r+8)*132 + cc+1] = acc[mt][nt][3];
    }
  __syncthreads();

  int z0 = zt * 128;
  for (int rr = wid; rr < 128; rr += 8){
    const float* src = Csh + rr*132;
    size_t ob = (size_t)(z0 + rr)*1152 + obase + kq;
    if (nk == 1){
      float4 v = *(const float4*)(src + lane*4);
      *(float4*)(out + ob + lane*4) = v;
    } else {
      #pragma unroll
      for (int j = 0; j < 4; ++j){
        int w = lane + j*32;
        out[ob + (size_t)w*nk] = src[w];
      }
    }
  }
}

// ---------------- launch ----------------
extern "C" void kernel_launch(void* const* d_in, const int* in_sizes, int n_in,
                              void* d_out, int out_size){
  const float* x = (const float*)d_in[0];
  const float* y = (const float*)d_in[1];
  const float* w = (const float*)d_in[2];
  float* out = (float*)d_out;
  int n = in_sizes[0] / 1152;   // 65536

  cudaFuncSetAttribute(gemm_mma, cudaFuncAttributeMaxDynamicSharedMemorySize, SMEM_SZ);

  cg_kernel<<<1, 32>>>();
  wprep<<<(3*128*640 + 255)/256, 256>>>(w);
  t_build<<<n / ZB, 256>>>(x, y);
  gemm_mma<<<(n / 128)    , 256, SMEM_SZ>>>(out, 0, 384, 1, 0);
  gemm_mma<<<(n / 128) * 3, 256, SMEM_SZ>>>(out, 1, 640, 3, 128);
  gemm_mma<<<(n / 128) * 5, 256, SMEM_SZ>>>(out, 2, 640, 5, 512);
}

// round 5
// speedup vs baseline: 2.0520x; 1.0891x over previous
#include <cuda_runtime.h>
#include <cuda_fp16.h>
#include <cstdint>

#define NPATH 13
#define SMEM_SZ 131072

// ---------------- static device scratch ----------------
__device__ __align__(256) float g_cg[573];
__device__ __align__(256) __half2 g_T0[65536ull*384];    // K'=768 interleaved (hi,lo)
__device__ __align__(256) __half2 g_T1[196608ull*640];   // K'=1280
__device__ __align__(256) __half2 g_T2[327680ull*640];   // K'=1280
__device__ __align__(256) __half2 g_W[3*128*640];        // B[n][kappa] = (h,h)

__device__ const int c_L1[NPATH]   = {0,0,0,1,1,1,1,1,2,2,2,2,2};
__device__ const int c_L2[NPATH]   = {0,1,2,0,1,1,2,3,0,1,2,2,3};
__device__ const int c_LO[NPATH]   = {0,1,2,1,0,2,1,2,2,1,0,2,1};
__device__ const int c_CGOFF[NPATH]= {0,1,10,35,44,53,98,143,248,273,318,343,468};
__device__ const int c_MSZ[NPATH]  = {1,3,5,9,3,15,9,15,25,15,5,25,15};
__device__ const int c_YOFF[4]     = {0,1,4,9};
__device__ const int c_PB[3][5] = {
  {0,      65536,  163840, 0,      0     },
  {16384,  49152,  98304,  147456, 196608},
  {32768,  81920,  114688, 131072, 180224}
};

// ---------------- CG computation (fp64, ported from reference) ----------------
__device__ double dfact(int n){ double r = 1.0; for (int i = 2; i <= n; ++i) r *= (double)i; return r; }

__device__ double su2_cg(int j1,int m1,int j2,int m2,int j3,int m3){
  if (m3 != m1 + m2) return 0.0;
  int vmin = max(max(-j1 + j2 + m3, -j1 + m1), 0);
  int vmax = min(min(j2 + j3 + m1, j3 - j1 + j2), j3 + m3);
  double C = sqrt((double)(2*j3+1) * dfact(j3+j1-j2) * dfact(j3-j1+j2) * dfact(j1+j2-j3)
                  * dfact(j3+m3) * dfact(j3-m3)
                  / (dfact(j1+j2+j3+1) * dfact(j1-m1) * dfact(j1+m1) * dfact(j2-m2) * dfact(j2+m2)));
  double S = 0.0;
  for (int v = vmin; v <= vmax; ++v){
    double sg = ((v + j2 + m2) & 1) ? -1.0 : 1.0;
    S += sg * dfact(j2+j3+m1-v) * dfact(j1-m1+v)
         / (dfact(v) * dfact(j3-j1+j2-v) * dfact(j3+m3-v) * dfact(v+j1-j2-m3));
  }
  return C * S;
}

__device__ void build_q(int l, double (*qr)[7], double (*qi)[7]){
  for (int a = 0; a < 7; ++a) for (int b = 0; b < 7; ++b){ qr[a][b] = 0.0; qi[a][b] = 0.0; }
  double s = 1.0 / sqrt(2.0);
  for (int m = -l; m < 0; ++m){ qr[l+m][l-m] = s; qi[l+m][l+m] = -s; }
  qr[l][l] = 1.0;
  for (int m = 1; m <= l; ++m){
    double sg = (m & 1) ? -1.0 : 1.0;
    qr[l+m][l+m] = sg * s; qi[l+m][l-m] = sg * s;
  }
  int ph = l & 3;
  if (ph){
    for (int a = 0; a < 2*l+1; ++a) for (int b = 0; b < 2*l+1; ++b){
      double re = qr[a][b], im = qi[a][b];
      if (ph == 1){ qr[a][b] =  im; qi[a][b] = -re; }
      else if (ph == 2){ qr[a][b] = -re; qi[a][b] = -im; }
      else { qr[a][b] = -im; qi[a][b] =  re; }
    }
  }
}

__global__ void cg_kernel(){
  int p = threadIdx.x;
  if (p >= NPATH) return;
  int l1 = c_L1[p], l2 = c_L2[p], l3 = c_LO[p];
  int d1 = 2*l1+1, d2 = 2*l2+1, d3 = 2*l3+1;

  double Ccg[5][7][5];
  for (int a = 0; a < 5; ++a) for (int b = 0; b < 7; ++b) for (int c = 0; c < 5; ++c) Ccg[a][b][c] = 0.0;
  for (int m1 = -l1; m1 <= l1; ++m1)
    for (int m2 = -l2; m2 <= l2; ++m2){
      int m3 = m1 + m2;
      if (m3 >= -l3 && m3 <= l3)
        Ccg[l1+m1][l2+m2][l3+m3] = su2_cg(l1, m1, l2, m2, l3, m3);
    }

  double q1r[7][7], q1i[7][7], q2r[7][7], q2i[7][7], q3r[7][7], q3i[7][7];
  build_q(l1, q1r, q1i); build_q(l2, q2r, q2i); build_q(l3, q3r, q3i);

  double outv[5][7][5];
  double norm2 = 0.0;
  for (int j = 0; j < d1; ++j)
    for (int l = 0; l < d2; ++l)
      for (int m = 0; m < d3; ++m){
        double re = 0.0;
        for (int i = 0; i < d1; ++i){
          double a1r = q1r[i][j], a1i = q1i[i][j];
          if (a1r == 0.0 && a1i == 0.0) continue;
          for (int k = 0; k < d2; ++k){
            double a2r = q2r[k][l], a2i = q2i[k][l];
            if (a2r == 0.0 && a2i == 0.0) continue;
            double ar = a1r*a2r - a1i*a2i;
            double ai = a1r*a2i + a1i*a2r;
            for (int n = 0; n < d3; ++n){
              double c = Ccg[i][k][n];
              if (c == 0.0) continue;
              re += c * (ar*q3r[n][m] - ai*(-q3i[n][m]));
            }
          }
        }
        outv[j][l][m] = re;
        norm2 += re * re;
      }
  double cio = (l3 == 0) ? sqrt(1.0/384.0) : (l3 == 1 ? sqrt(3.0/640.0) : sqrt(5.0/640.0));
  double inv = cio / sqrt(norm2);
  for (int j = 0; j < d1; ++j)
    for (int l = 0; l < d2; ++l)
      for (int m = 0; m < d3; ++m)
        g_cg[c_CGOFF[p] + (j*d2 + l)*d3 + m] = (float)(outv[j][l][m] * inv);
}

// ---------------- weight prep: B[n][kappa] = (h, h) ----------------
__global__ void wprep(const float* __restrict__ w){
  int idx = blockIdx.x * 256 + threadIdx.x;
  if (idx >= 3*128*640) return;
  int g = idx / (128*640);
  int rem = idx - g*128*640;
  int n = rem / 640, k = rem % 640;
  int K = (g == 0) ? 384 : 640;
  float v = 0.f;
  if (k < K) v = w[c_PB[g][k >> 7] + (k & 127)*128 + n];
  __half h = __float2half_rn(v);
  g_W[idx] = __halves2half2(h, h);
}

// ---------------- T build ----------------
__device__ __forceinline__ void wsp2(__half2* p, float v){
  __half h = __float2half_rn(v);
  __half l = __float2half_rn(v - __half2float(h));
  *p = __halves2half2(h, l);
}

#define ZB 8
__global__ void __launch_bounds__(256) t_build(const float* __restrict__ x,
                                               const float* __restrict__ y){
  __shared__ float xs[ZB * 1152];
  __shared__ float ys[ZB * 16];
  __shared__ float Ms[ZB * 145];

  int z0  = blockIdx.x * ZB;
  int tid = threadIdx.x;

  for (int idx = tid; idx < ZB*1152; idx += 256) xs[idx] = x[(size_t)z0*1152 + idx];
  for (int idx = tid; idx < ZB*16;   idx += 256) ys[idx] = y[(size_t)z0*16 + idx];
  __syncthreads();

  for (int idx = tid; idx < ZB*145; idx += 256){
    int zl = idx / 145, e0 = idx % 145;
    int e = e0, p = 0;
    while (e >= c_MSZ[p]){ e -= c_MSZ[p]; ++p; }
    int l2 = c_L2[p], lo = c_LO[p];
    int d2 = 2*l2+1, dlo = 2*lo+1;
    int i = e / dlo, k = e % dlo;
    const float* cg = g_cg + c_CGOFF[p] + (i*d2)*dlo + k;
    const float* yy = ys + zl*16 + c_YOFF[l2];
    float s = 0.f;
    for (int j = 0; j < d2; ++j) s += cg[j*dlo] * yy[j];
    Ms[zl*145 + e0] = s;
  }
  __syncthreads();

  int u  = tid & 127;
  int zh = tid >> 7;
  for (int zl = zh; zl < ZB; zl += 2){
    const float* xz = xs + zl*1152;
    const float* M  = Ms + zl*145;
    float x0 = xz[u];
    float xa = xz[128 + u*3 + 0], xb = xz[128 + u*3 + 1], xc = xz[128 + u*3 + 2];
    float x2v[5];
    #pragma unroll
    for (int i = 0; i < 5; ++i) x2v[i] = xz[512 + u*5 + i];
    size_t z = z0 + zl;

    { // io0: row = z, 3 pl blocks
      __half2* T = g_T0 + z*384 + u;
      wsp2(T,       x0 * M[0]);
      wsp2(T + 128, xa*M[18] + xb*M[19] + xc*M[20]);
      float s = 0.f;
      #pragma unroll
      for (int i = 0; i < 5; ++i) s += x2v[i] * M[100 + i];
      wsp2(T + 256, s);
    }
    #pragma unroll
    for (int k = 0; k < 3; ++k){ // io1: row = z*3+k, 5 pl blocks
      __half2* T = g_T1 + (z*3 + k)*640 + u;
      wsp2(T,       x0 * M[1 + k]);
      wsp2(T + 128, xa*M[9 + k] + xb*M[12 + k] + xc*M[15 + k]);
      wsp2(T + 256, xa*M[36 + k] + xb*M[39 + k] + xc*M[42 + k]);
      float s3 = 0.f, s4 = 0.f;
      #pragma unroll
      for (int i = 0; i < 5; ++i){ s3 += x2v[i]*M[85 + i*3 + k]; s4 += x2v[i]*M[130 + i*3 + k]; }
      wsp2(T + 384, s3);
      wsp2(T + 512, s4);
    }
    #pragma unroll
    for (int k = 0; k < 5; ++k){ // io2: row = z*5+k
      __half2* T = g_T2 + (z*5 + k)*640 + u;
      wsp2(T,       x0 * M[4 + k]);
      wsp2(T + 128, xa*M[21 + k] + xb*M[26 + k] + xc*M[31 + k]);
      wsp2(T + 256, xa*M[45 + k] + xb*M[50 + k] + xc*M[55 + k]);
      float s3 = 0.f, s4 = 0.f;
      #pragma unroll
      for (int i = 0; i < 5; ++i){ s3 += x2v[i]*M[60 + i*5 + k]; s4 += x2v[i]*M[105 + i*5 + k]; }
      wsp2(T + 384, s3);
      wsp2(T + 512, s4);
    }
  }
}

// ---------------- mma.sync GEMM, 4-stage cp.async pipeline ----------------
__device__ __forceinline__ uint32_t smem_u32(const void* p){
  uint32_t a;
  asm("{ .reg .u64 t; cvta.to.shared.u64 t, %1; cvt.u32.u64 %0, t; }" : "=r"(a) : "l"(p));
  return a;
}
#define SWZ(off) ((off) ^ (((off) >> 3) & 0x70))

__device__ __forceinline__ void cp16(uint32_t dst, const void* src){
  asm volatile("cp.async.cg.shared.global [%0], [%1], 16;" :: "r"(dst), "l"(src) : "memory");
}
__device__ __forceinline__ void cp_commit(){ asm volatile("cp.async.commit_group;" ::: "memory"); }
template<int N> __device__ __forceinline__ void cp_wait(){ asm volatile("cp.async.wait_group %0;" :: "n"(N) : "memory"); }

__device__ __forceinline__ void ldsm4(uint32_t* r, uint32_t addr){
  asm volatile("ldmatrix.sync.aligned.m8n8.x4.shared.b16 {%0,%1,%2,%3}, [%4];"
    : "=r"(r[0]), "=r"(r[1]), "=r"(r[2]), "=r"(r[3]) : "r"(addr));
}
__device__ __forceinline__ void mma16816(float* c, const uint32_t* a, uint32_t b0, uint32_t b1){
  asm volatile("mma.sync.aligned.m16n8k16.row.col.f32.f16.f16.f32 "
    "{%0,%1,%2,%3}, {%4,%5,%6,%7}, {%8,%9}, {%0,%1,%2,%3};"
    : "+f"(c[0]), "+f"(c[1]), "+f"(c[2]), "+f"(c[3])
    : "r"(a[0]), "r"(a[1]), "r"(a[2]), "r"(a[3]), "r"(b0), "r"(b1));
}

__global__ void __launch_bounds__(256, 1) gemm_mma(float* __restrict__ out,
                                                   int io, int Kp, int nk, int obase){
  extern __shared__ __align__(1024) char smem[];
  uint32_t sb = smem_u32(smem);
  int tid = threadIdx.x, wid = tid >> 5, lane = tid & 31;

  const __half* pA = (io == 0) ? (const __half*)g_T0 : (io == 1) ? (const __half*)g_T1 : (const __half*)g_T2;
  const __half* pB = (const __half*)(g_W + io*128*640);
  size_t strideA = (io == 0) ? 768 : 1280;   // halves per A row (= K')
  size_t R0 = (size_t)blockIdx.x * 128;
  int C = Kp / 64;

  int m0 = (wid & 3) * 32;
  int n0 = (wid >> 2) * 64;

  float acc[2][8][4];
  #pragma unroll
  for (int a = 0; a < 2; ++a)
    #pragma unroll
    for (int b = 0; b < 8; ++b)
      #pragma unroll
      for (int c = 0; c < 4; ++c) acc[a][b][c] = 0.f;

  // fragment addressing (validated R4)
  int rA = (lane & 7) + (lane & 8);
  int cAb = (lane >> 4) << 4;
  int rB = (lane & 7) + ((lane >> 4) << 3);
  int cBb = ((lane >> 3) & 1) << 4;

  #define ISSUE(c_) do{                                                     \
    int s_ = (c_) & 3;                                                      \
    uint32_t stA_ = sb + s_*32768u, stB_ = stA_ + 16384u;                   \
    int k0_ = (c_) * 64;                                                    \
    _Pragma("unroll")                                                       \
    for (int i_ = 0; i_ < 4; ++i_){                                         \
      int idx_ = tid + i_*256;                                              \
      int r_ = idx_ >> 3, sg_ = idx_ & 7;                                   \
      cp16(stA_ + SWZ(r_*128 + sg_*16), pA + (R0 + r_)*strideA + k0_ + sg_*8); \
      cp16(stB_ + SWZ(r_*128 + sg_*16), pB + (size_t)r_*1280 + k0_ + sg_*8);   \
    }                                                                       \
    cp_commit();                                                            \
  }while(0)

  ISSUE(0); ISSUE(1); ISSUE(2);

  for (int c = 0; c < C; ++c){
    __syncthreads();                 // all warps done with stage (c+3)&3's previous occupant
    if (c + 3 < C){ ISSUE(c + 3); cp_wait<3>(); }
    else {
      int rem = C - 1 - c;
      if (rem >= 2) cp_wait<2>(); else if (rem == 1) cp_wait<1>(); else cp_wait<0>();
    }
    __syncthreads();

    uint32_t stA = sb + (uint32_t)(c & 3)*32768u;
    uint32_t stB = stA + 16384u;
    #pragma unroll
    for (int kk = 0; kk < 4; ++kk){
      int cb = kk*32;
      uint32_t afr[2][4];
      #pragma unroll
      for (int mt = 0; mt < 2; ++mt)
        ldsm4(afr[mt], stA + SWZ((m0 + mt*16 + rA)*128 + cb + cAb));
      uint32_t bfr[4][4];
      #pragma unroll
      for (int bt = 0; bt < 4; ++bt)
        ldsm4(bfr[bt], stB + SWZ((n0 + bt*16 + rB)*128 + cb + cBb));
      #pragma unroll
      for (int mt = 0; mt < 2; ++mt)
        #pragma unroll
        for (int nt = 0; nt < 8; ++nt){
          int bt = nt >> 1, rp = (nt & 1) * 2;
          mma16816(acc[mt][nt], afr[mt], bfr[bt][rp], bfr[bt][rp+1]);
        }
    }
  }
  __syncthreads();

  // epilogue: accumulators -> smem -> global (z-major rows => L2-mergeable)
  float* Csh = (float*)smem;   // [128][132]
  #pragma unroll
  for (int mt = 0; mt < 2; ++mt)
    #pragma unroll
    for (int nt = 0; nt < 8; ++nt){
      int r = m0 + mt*16 + (lane >> 2);
      int cc = n0 + nt*8 + (lane & 3)*2;
      Csh[r*132 + cc]       = acc[mt][nt][0];
      Csh[r*132 + cc + 1]   = acc[mt][nt][1];
      Csh[(r+8)*132 + cc]   = acc[mt][nt][2];
      Csh[(r+8)*132 + cc+1] = acc[mt][nt][3];
    }
  __syncthreads();

  for (int rr = wid; rr < 128; rr += 8){
    const float* src = Csh + rr*132;
    int rg = (int)R0 + rr;
    int z = rg / nk, kq = rg % nk;
    size_t base = (size_t)z*1152 + obase + kq;
    if (nk == 1){
      float4 v = *(const float4*)(src + lane*4);
      *(float4*)(out + base + lane*4) = v;
    } else {
      #pragma unroll
      for (int j = 0; j < 4; ++j){
        int w = lane + j*32;
        out[base + (size_t)w*nk] = src[w];
      }
    }
  }
  #undef ISSUE
}

// ---------------- launch ----------------
extern "C" void kernel_launch(void* const* d_in, const int* in_sizes, int n_in,
                              void* d_out, int out_size){
  const float* x = (const float*)d_in[0];
  const float* y = (const float*)d_in[1];
  const float* w = (const float*)d_in[2];
  float* out = (float*)d_out;
  int n = in_sizes[0] / 1152;   // 65536

  cudaFuncSetAttribute(gemm_mma, cudaFuncAttributeMaxDynamicSharedMemorySize, SMEM_SZ);

  cg_kernel<<<1, 32>>>();
  wprep<<<(3*128*640 + 255)/256, 256>>>(w);
  t_build<<<n / ZB, 256>>>(x, y);
  gemm_mma<<<(n / 128)    , 256, SMEM_SZ>>>(out, 0, 768,  1, 0);
  gemm_mma<<<(n / 128) * 3, 256, SMEM_SZ>>>(out, 1, 1280, 3, 128);
  gemm_mma<<<(n / 128) * 5, 256, SMEM_SZ>>>(out, 2, 1280, 5, 512);
}